// round 11
// baseline (speedup 1.0000x reference)
#include <cuda_runtime.h>
#include <cuda_fp16.h>
#include <cstdint>
#include <math.h>

#define BB 8
#define LL 512
#define DD 4096
#define HH 8
#define FF 16384
#define AA 512       // per-head dim == L
#define MM (BB*LL)   // 4096

// ---------------- scratch (device globals: allocation-free) ----------------
__device__ __align__(16) __half g_xnb[MM*DD];        // ln1 out fp16
__device__ __align__(16) __half g_xn2[MM*DD];        // ln2 out fp16
__device__ __align__(16) __half g_q  [HH*MM*AA];     // q  [h][m][a]
__device__ __align__(16) __half g_kTq[HH*AA*MM];     // kT quad-packed
__device__ __align__(16) __half g_vT [HH*AA*MM];     // vT plain [h][a][m]
__device__ __align__(16) float  g_s  [HH*BB*LL*LL];  // scores fp32
__device__ __align__(16) __half g_att[MM*DD];        // attention concat fp16
__device__ __align__(16) float  g_x1 [MM*DD];        // residual fp32
__device__ __align__(16) __half g_h  [MM*FF];        // MLP hidden fp16
// prepped weights (fp16, quad-packed along K)
__device__ __align__(16) __half g_wqkv[3*HH*DD*AA];
__device__ __align__(16) __half g_wfc [DD*DD];
__device__ __align__(16) __half g_w1  [DD*FF];
__device__ __align__(16) __half g_w2  [FF*DD];

// ---------------- helpers ----------------
__device__ __forceinline__ uint32_t pack_hf(float lo, float hi) {
    __half2 h = __floats2half2_rn(lo, hi);
    return *(uint32_t*)&h;
}
__device__ __forceinline__ float gelu_exact(float x) {
    return 0.5f * x * (1.0f + erff(x * 0.7071067811865475f));
}
__device__ __forceinline__ uint32_t sptr(const void* p) {
    return (uint32_t)__cvta_generic_to_shared(p);
}
__device__ __forceinline__ void cp16(void* dst, const void* src) {
    asm volatile("cp.async.cg.shared.global [%0], [%1], 16;" :: "r"(sptr(dst)), "l"(src));
}
__device__ __forceinline__ void cp_commit() {
    asm volatile("cp.async.commit_group;");
}
template<int N>
__device__ __forceinline__ void cp_wait() {
    asm volatile("cp.async.wait_group %0;" :: "n"(N));
}

// ---------------- quad-pack layout ----------------
// B[k][n]: word32(k=2p,2p+1 @ n) at (p>>3)*(8N) + (p&3)*(2N) + n*2 + ((p>>2)&1)
__device__ __forceinline__ void pack_one(const float* __restrict__ in,
                                         __half* __restrict__ out,
                                         long long pairidx, int nl)
{
    long long N = 1LL << nl;
    long long p = pairidx >> nl;
    long long n = pairidx & (N - 1);
    float v0 = in[(2 * p) * N + n];
    float v1 = in[(2 * p + 1) * N + n];
    long long w = (p >> 3) * (8 * N) + (p & 3) * (2 * N) + n * 2 + ((p >> 2) & 1);
    *(uint32_t*)(out + 2 * w) = pack_hf(v0, v1);
}

#define QP  ((long long)HH*DD*AA/2)
#define FCP ((long long)DD*DD/2)
#define W1P ((long long)DD/2*FF)
#define W2P ((long long)FF/2*DD)
#define PREP_PAIRS (3*QP + FCP + W1P + W2P)

__global__ void prep_weights(const float* __restrict__ Wq, const float* __restrict__ Wk,
                             const float* __restrict__ Wv, const float* __restrict__ Wfc,
                             const float* __restrict__ W1, const float* __restrict__ W2,
                             __half* __restrict__ wqkv, __half* __restrict__ wfc,
                             __half* __restrict__ w1, __half* __restrict__ w2)
{
    long long i = (long long)blockIdx.x * blockDim.x + threadIdx.x;
    if (i < 3 * QP) {
        int w = (int)(i / QP);
        long long r = i - (long long)w * QP;
        const float* src = (w == 0) ? Wq : (w == 1) ? Wk : Wv;
        pack_one(src, wqkv + (long long)w * (2 * QP), r, 9);
    } else if (i < 3 * QP + FCP) {
        pack_one(Wfc, wfc, i - 3 * QP, 12);
    } else if (i < 3 * QP + FCP + W1P) {
        pack_one(W1, w1, i - (3 * QP + FCP), 14);
    } else {
        pack_one(W2, w2, i - (3 * QP + FCP + W1P), 12);
    }
}

// ---------------- layernorm (fp16 output) ----------------
__global__ void ln_kernel(const float* __restrict__ x,
                          const float* __restrict__ g,
                          const float* __restrict__ b,
                          __half* __restrict__ outb)
{
    int row = blockIdx.x;
    const float4* xr = (const float4*)(x + (size_t)row * DD);
    __shared__ float red[256];
    float4 vals[4];
    float s = 0.f;
#pragma unroll
    for (int it = 0; it < 4; ++it) {
        float4 v = xr[threadIdx.x + it * 256];
        vals[it] = v;
        s += v.x + v.y + v.z + v.w;
    }
    red[threadIdx.x] = s; __syncthreads();
    for (int st = 128; st > 0; st >>= 1) {
        if (threadIdx.x < st) red[threadIdx.x] += red[threadIdx.x + st];
        __syncthreads();
    }
    float mean = red[0] * (1.f / DD);
    __syncthreads();
    float vs = 0.f;
#pragma unroll
    for (int it = 0; it < 4; ++it) {
        float4 v = vals[it];
        float dx = v.x - mean, dy = v.y - mean, dz = v.z - mean, dw = v.w - mean;
        vs += dx*dx + dy*dy + dz*dz + dw*dw;
    }
    red[threadIdx.x] = vs; __syncthreads();
    for (int st = 128; st > 0; st >>= 1) {
        if (threadIdx.x < st) red[threadIdx.x] += red[threadIdx.x + st];
        __syncthreads();
    }
    float rstd = rsqrtf(red[0] * (1.f / DD) + 1e-5f);
#pragma unroll
    for (int it = 0; it < 4; ++it) {
        int c = (threadIdx.x + it * 256) * 4;
        float4 v = vals[it];
        float4 gg = *(const float4*)(g + c);
        float4 bb = *(const float4*)(b + c);
        float rx = (v.x - mean) * rstd * gg.x + bb.x;
        float ry = (v.y - mean) * rstd * gg.y + bb.y;
        float rz = (v.z - mean) * rstd * gg.z + bb.z;
        float rw = (v.w - mean) * rstd * gg.w + bb.w;
        uint32_t* o = (uint32_t*)(outb + (size_t)row * DD);
        o[(threadIdx.x + it * 256) * 2 + 0] = pack_hf(rx, ry);
        o[(threadIdx.x + it * 256) * 2 + 1] = pack_hf(rz, rw);
    }
}

// =====================================================================
// fp16 GEMM (m16n8k16, fp32 accum): C = A[M,K] @ B (B quad-packed)
// 128x128x64 CTA tile, 128 threads, 4 warps of 64x64, 3-stage cp.async.
// A fragments via LDS.32; B fragments via LDS.64 (quad layout, conflict-free
// stride). Fragment registers double-buffered across ksg (prefetch ksg+1
// during ksg's MMAs).
// EPI: 0 raw fp32, 4 bias+residual fp32, 5 bias+gelu fp16,
//      6 merged QKV (dispatch on z>>3: 0->plain, 1->quadT, 2->plainT)
// =====================================================================
#define BA_STRIDE 144              // bytes per A row (128 data + 16 pad)
#define BQ_STRIDE 1056             // bytes per B qrow (1024 data + 32 pad) — /8 ≡ 4 (mod 16): conflict-free LDS.64
#define BA_TILE (128 * BA_STRIDE)  // 18432
#define BQ_TILE (16 * BQ_STRIDE)   // 16896
#define BSTAGE (BA_TILE + BQ_TILE) // 35328
#define HF_SMEM (3 * BSTAGE)       // 105984

template<int EPI>
__global__ void __launch_bounds__(128, 2)
gemm_hf(const __half* __restrict__ A, const __half* __restrict__ Bq,
        float* __restrict__ Cf, __half* __restrict__ Cb,
        __half* __restrict__ Cb2, __half* __restrict__ Cb3,
        const float* __restrict__ bias, const float* __restrict__ res,
        int M, int N, int K, int ldq, int zdiv,
        long long sA, long long sB, long long sB2, long long sC)
{
    extern __shared__ char smem[];

    int z = blockIdx.z;
    A  += (long long)z * sA;
    Bq += (long long)(z / zdiv) * sB + (long long)(z % zdiv) * sB2;
    long long co = (EPI == 6) ? (long long)(z & 7) * sC : (long long)z * sC;
    int which = z >> 3;   // used only by EPI 6

    int m0 = blockIdx.y * 128, n0 = blockIdx.x * 128;
    int tid = threadIdx.x;
    int warp = tid >> 5, lane = tid & 31;
    int wm = (warp >> 1) * 64, wn = (warp & 1) * 64;
    int gid = lane >> 2, tig = lane & 3;

    float acc[4][8][4];
#pragma unroll
    for (int a = 0; a < 4; ++a)
#pragma unroll
        for (int b = 0; b < 8; ++b)
#pragma unroll
            for (int c = 0; c < 4; ++c) acc[a][b][c] = 0.f;

    const int T = K >> 6;

    auto load_tile = [&](int t, int st) {
        char* As = smem + st * BSTAGE;
        char* Bs = As + BA_TILE;
#pragma unroll
        for (int i = 0; i < 8; ++i) {          // A: 128 rows x 8 chunks of 16B
            int idx = tid + i * 128;
            int r = idx >> 3, c = idx & 7;
            cp16(As + r * BA_STRIDE + c * 16,
                 A + (size_t)(m0 + r) * K + t * 64 + c * 8);
        }
#pragma unroll
        for (int i = 0; i < 8; ++i) {          // B: 16 qrows x 64 chunks of 16B
            int idx = tid + i * 128;
            int qr = idx >> 6, ch = idx & 63;
            cp16(Bs + qr * BQ_STRIDE + ch * 16,
                 Bq + (size_t)(t * 16 + qr) * ldq + (size_t)n0 * 4 + ch * 8);
        }
    };

    load_tile(0, 0);
    cp_commit();
    if (T > 1) load_tile(1, 1);
    cp_commit();

    uint32_t af[2][4][4];
    uint2    bf[2][8];

    int st = 0;
    for (int t = 0; t < T; ++t) {
        cp_wait<1>();
        __syncthreads();
        int st2 = st + 2; if (st2 >= 3) st2 -= 3;
        if (t + 2 < T) load_tile(t + 2, st2);
        cp_commit();

        const char* As = smem + st * BSTAGE;
        const char* Bs = As + BA_TILE;
        const char* Abase = As + (wm + gid) * BA_STRIDE + tig * 4;
        const char* Bbase = Bs + tig * BQ_STRIDE + (wn + gid) * 8;

        // fragment loader for one ksg into buffer `buf`
        auto load_frags = [&](int ksg, int buf) {
            const char* ab = Abase + ksg * 32;
#pragma unroll
            for (int mf = 0; mf < 4; ++mf) {
                const char* p = ab + mf * 16 * BA_STRIDE;
                af[buf][mf][0] = *(const uint32_t*)(p);
                af[buf][mf][1] = *(const uint32_t*)(p + 8 * BA_STRIDE);
                af[buf][mf][2] = *(const uint32_t*)(p + 16);
                af[buf][mf][3] = *(const uint32_t*)(p + 8 * BA_STRIDE + 16);
            }
            const char* brow = Bbase + ksg * 4 * BQ_STRIDE;
#pragma unroll
            for (int nf = 0; nf < 8; ++nf)
                bf[buf][nf] = *(const uint2*)(brow + nf * 64);
        };

        load_frags(0, 0);
#pragma unroll
        for (int ksg = 0; ksg < 4; ++ksg) {
            if (ksg < 3) load_frags(ksg + 1, (ksg + 1) & 1);
            int buf = ksg & 1;
#pragma unroll
            for (int nf = 0; nf < 8; ++nf) {
#pragma unroll
                for (int mf = 0; mf < 4; ++mf) {
                    asm volatile(
                        "mma.sync.aligned.m16n8k16.row.col.f32.f16.f16.f32 "
                        "{%0,%1,%2,%3}, {%4,%5,%6,%7}, {%8,%9}, {%0,%1,%2,%3};"
                        : "+f"(acc[mf][nf][0]), "+f"(acc[mf][nf][1]),
                          "+f"(acc[mf][nf][2]), "+f"(acc[mf][nf][3])
                        : "r"(af[buf][mf][0]), "r"(af[buf][mf][1]),
                          "r"(af[buf][mf][2]), "r"(af[buf][mf][3]),
                          "r"(bf[buf][nf].x), "r"(bf[buf][nf].y));
                }
            }
        }
        if (++st >= 3) st = 0;
    }

    // ---- epilogue ----
    float* CF = Cf + co;
#pragma unroll
    for (int mf = 0; mf < 4; ++mf) {
        int r0 = m0 + wm + mf * 16 + gid;
#pragma unroll
        for (int nf = 0; nf < 8; ++nf) {
            int c = n0 + wn + nf * 8 + tig * 2;
#pragma unroll
            for (int half = 0; half < 2; ++half) {
                int r = r0 + half * 8;
                float v0 = acc[mf][nf][half * 2 + 0];
                float v1 = acc[mf][nf][half * 2 + 1];
                if (EPI == 0) {
                    *(float2*)(CF + (size_t)r * N + c) = make_float2(v0, v1);
                } else if (EPI == 4) {
                    v0 += bias[c]; v1 += bias[c + 1];
                    size_t off = (size_t)r * N + c;
                    v0 += res[off]; v1 += res[off + 1];
                    *(float2*)(CF + off) = make_float2(v0, v1);
                } else if (EPI == 5) {   // bias + gelu -> fp16
                    v0 = gelu_exact(v0 + bias[c]);
                    v1 = gelu_exact(v1 + bias[c + 1]);
                    *(uint32_t*)(Cb + co + (size_t)r * N + c) = pack_hf(v0, v1);
                } else if (EPI == 6) {
                    if (which == 0) {          // q: plain fp16 [m][a]
                        *(uint32_t*)(Cb + co + (size_t)r * N + c) = pack_hf(v0, v1);
                    } else if (which == 1) {   // kT: quad-packed, k-dim=c, n-dim=r
                        size_t w = (size_t)(c >> 4) * (8 * (size_t)M)
                                 + (size_t)((c >> 1) & 3) * (2 * (size_t)M)
                                 + (size_t)r * 2 + ((c >> 3) & 1);
                        *(uint32_t*)(Cb2 + co + 2 * w) = pack_hf(v0, v1);
                    } else {                   // vT: plain transposed
                        Cb3[co + (size_t)c * M + r]       = __float2half(v0);
                        Cb3[co + (size_t)(c + 1) * M + r] = __float2half(v1);
                    }
                }
            }
        }
    }
}

// ---------------- column softmax + p * v^T + head concat -> att (fp16) ----------------
__global__ void softmax_att_kernel(const float* __restrict__ s,
                                   const __half* __restrict__ vT,
                                   __half* __restrict__ att)
{
    int z = blockIdx.y;          // z = h*B + b
    int h = z >> 3, b = z & 7;
    int j0 = blockIdx.x * 32;
    int tx = threadIdx.x, ty = threadIdx.y;   // 32 x 16
    const float* sp = s + (size_t)z * LL * LL;
    const float rs = 0.04419417382415922f;    // 1/sqrt(512)
    int j = j0 + tx;

    float part = 0.f;
    for (int it = 0; it < 32; ++it) {
        int i = it * 16 + ty;
        float val = (j <= i) ? sp[(size_t)i * LL + j] : -1000.f;
        part += expf(val * rs);
    }
    __shared__ float red[16][32];
    __shared__ float cinv[32];
    red[ty][tx] = part; __syncthreads();
    if (ty < 8) red[ty][tx] += red[ty + 8][tx];
    __syncthreads();
    if (ty < 4) red[ty][tx] += red[ty + 4][tx];
    __syncthreads();
    if (ty < 2) red[ty][tx] += red[ty + 2][tx];
    __syncthreads();
    if (ty == 0) cinv[tx] = 1.f / (red[0][tx] + red[1][tx]);
    __syncthreads();
    float ci = cinv[tx];

    const __half* vrow = vT + (size_t)h * AA * MM + (size_t)b * LL + j;
    size_t attb = (size_t)b * LL * DD + (size_t)h * AA + j;
    for (int it = 0; it < 32; ++it) {
        int i = it * 16 + ty;
        float val = (j <= i) ? sp[(size_t)i * LL + j] : -1000.f;
        float p = expf(val * rs) * ci;
        float vv = __half2float(vrow[(size_t)i * MM]);
        att[attb + (size_t)i * DD] = __float2half(p * vv);
    }
}

// ---------------- launch ----------------
extern "C" void kernel_launch(void* const* d_in, const int* in_sizes, int n_in,
                              void* d_out, int out_size)
{
    (void)in_sizes; (void)n_in; (void)out_size;
    const float* x    = (const float*)d_in[0];
    const float* Wq   = (const float*)d_in[2];
    const float* Wk   = (const float*)d_in[3];
    const float* Wv   = (const float*)d_in[4];
    const float* fc_w = (const float*)d_in[5];
    const float* fc_b = (const float*)d_in[6];
    const float* ln1g = (const float*)d_in[7];
    const float* ln1b = (const float*)d_in[8];
    const float* W1   = (const float*)d_in[9];
    const float* b1   = (const float*)d_in[10];
    const float* W2   = (const float*)d_in[11];
    const float* b2   = (const float*)d_in[12];
    const float* ln2g = (const float*)d_in[13];
    const float* ln2b = (const float*)d_in[14];
    float* out = (float*)d_out;

    float *s, *x1;
    __half *xnb, *xn2, *q, *kTq, *vT, *att, *hb, *wqkv, *wfc, *w1, *w2;
    cudaGetSymbolAddress((void**)&xnb,  g_xnb);
    cudaGetSymbolAddress((void**)&xn2,  g_xn2);
    cudaGetSymbolAddress((void**)&q,    g_q);
    cudaGetSymbolAddress((void**)&kTq,  g_kTq);
    cudaGetSymbolAddress((void**)&vT,   g_vT);
    cudaGetSymbolAddress((void**)&s,    g_s);
    cudaGetSymbolAddress((void**)&att,  g_att);
    cudaGetSymbolAddress((void**)&x1,   g_x1);
    cudaGetSymbolAddress((void**)&hb,   g_h);
    cudaGetSymbolAddress((void**)&wqkv, g_wqkv);
    cudaGetSymbolAddress((void**)&wfc,  g_wfc);
    cudaGetSymbolAddress((void**)&w1,   g_w1);
    cudaGetSymbolAddress((void**)&w2,   g_w2);

    cudaFuncSetAttribute(gemm_hf<0>, cudaFuncAttributeMaxDynamicSharedMemorySize, HF_SMEM);
    cudaFuncSetAttribute(gemm_hf<4>, cudaFuncAttributeMaxDynamicSharedMemorySize, HF_SMEM);
    cudaFuncSetAttribute(gemm_hf<5>, cudaFuncAttributeMaxDynamicSharedMemorySize, HF_SMEM);
    cudaFuncSetAttribute(gemm_hf<6>, cudaFuncAttributeMaxDynamicSharedMemorySize, HF_SMEM);

    const long long HAM = (long long)AA * MM;

    // launch 0: ln1
    ln_kernel<<<MM, 256>>>(x, ln1g, ln1b, xnb);

    // launch 1: fused weight prep (fp16 quad-pack, all weights)
    prep_weights<<<(unsigned)(PREP_PAIRS / 256), 256>>>(
        Wq, Wk, Wv, fc_w, W1, W2, wqkv, wfc, w1, w2);

    // launch 2: merged QKV (z = which*8 + head, 3072 CTAs)
    {
        dim3 grid(AA / 128, MM / 128, 3 * HH);
        gemm_hf<6><<<grid, 128, HF_SMEM>>>(xnb, wqkv, nullptr, q, kTq, vT,
                                           nullptr, nullptr,
                                           MM, AA, DD, 4 * AA, 1,
                                           0, (long long)DD * AA, 0, (long long)MM * AA);
    }

    // launch 3: S = q @ k^T (64 batches, z = h*8 + b)
    {
        dim3 grid(LL / 128, LL / 128, HH * BB);
        gemm_hf<0><<<grid, 128, HF_SMEM>>>(q, kTq, s, nullptr, nullptr, nullptr,
                                           nullptr, nullptr,
                                           LL, LL, AA, 4 * MM, 8,
                                           (long long)LL * AA, HAM, 4LL * LL,
                                           (long long)LL * LL);
    }

    // launch 4: column softmax + p*v^T + concat
    {
        dim3 grid(LL / 32, HH * BB);
        dim3 blk(32, 16);
        softmax_att_kernel<<<grid, blk>>>(s, vT, att);
    }

    // launch 5: x1 = x + att @ fc_w + fc_b
    {
        dim3 grid(DD / 128, MM / 128, 1);
        gemm_hf<4><<<grid, 128, HF_SMEM>>>(att, wfc, x1, nullptr, nullptr, nullptr,
                                           fc_b, x,
                                           MM, DD, DD, 4 * DD, 1,
                                           0, 0, 0, 0);
    }

    // launch 6: ln2
    ln_kernel<<<MM, 256>>>(x1, ln2g, ln2b, xn2);

    // launch 7: h = gelu(xn2 @ W1 + b1) -> fp16
    {
        dim3 grid(FF / 128, MM / 128, 1);
        gemm_hf<5><<<grid, 128, HF_SMEM>>>(xn2, w1, nullptr, hb, nullptr, nullptr,
                                           b1, nullptr,
                                           MM, FF, DD, 4 * FF, 1,
                                           0, 0, 0, 0);
    }

    // launch 8: out = x1 + h @ W2 + b2
    {
        dim3 grid(DD / 128, MM / 128, 1);
        gemm_hf<4><<<grid, 128, HF_SMEM>>>(hb, w2, out, nullptr, nullptr, nullptr,
                                           b2, x1,
                                           MM, DD, FF, 4 * DD, 1,
                                           0, 0, 0, 0);
    }
}